// round 9
// baseline (speedup 1.0000x reference)
#include <cuda_runtime.h>
#include <math.h>

#define Tt   512
#define Bb   64
#define INN  128
#define Hh   512
#define Ll   3
#define OUTN 128

// ---------------- scratch (device globals: no runtime allocation) ----------
__device__ float g_bufA[Tt * Bb * Hh];   // 64 MB activation ping
__device__ float g_bufB[Tt * Bb * Hh];   // 64 MB activation pong

// ---------------- packed fp32x2 helpers (B300 FFMA2 path) ------------------
typedef unsigned long long ull;
#define FMA2(d, a, b) asm("fma.rn.f32x2 %0, %1, %2, %0;" : "+l"(d) : "l"(a), "l"(b))
#define UNPK(lo, hi, p) asm("mov.b64 {%0, %1}, %2;" : "=f"(lo), "=f"(hi) : "l"(p))

__device__ __forceinline__ unsigned cvta_smem(const void* p) {
    unsigned a;
    asm("{ .reg .u64 t; cvta.to.shared.u64 t, %1; cvt.u32.u64 %0, t; }"
        : "=r"(a) : "l"(p));
    return a;
}
__device__ __forceinline__ unsigned mapa_u32(unsigned addr, unsigned rank) {
    unsigned r;
    asm("mapa.shared::cluster.u32 %0, %1, %2;" : "=r"(r) : "r"(addr), "r"(rank));
    return r;
}
// bulk smem -> peer smem copy, tx-accounted on the PEER's mbarrier
__device__ __forceinline__ void bulk_s2c(unsigned dst, unsigned src,
                                         unsigned bytes, unsigned rbar) {
    asm volatile(
        "cp.async.bulk.shared::cluster.shared::cta.mbarrier::complete_tx::bytes "
        "[%0], [%1], %2, [%3];"
        :: "r"(dst), "r"(src), "r"(bytes), "r"(rbar) : "memory");
}
#define MBAR_INIT(a, n) \
    asm volatile("mbarrier.init.shared.b64 [%0], %1;" :: "r"(a), "r"(n) : "memory")
#define MBAR_EXPECT_TX(a, tx) \
    asm volatile("mbarrier.arrive.expect_tx.shared.b64 _, [%0], %1;" \
                 :: "r"(a), "r"(tx) : "memory")
#define MBAR_WAIT_CLUSTER(a, ph) do {                                          \
    unsigned _dn;                                                              \
    asm volatile("{\n\t.reg .pred p;\n\t"                                      \
        "mbarrier.try_wait.parity.acquire.cluster.shared::cta.b64 p, [%1], %2;\n\t" \
        "selp.b32 %0, 1, 0, p;\n\t}"                                           \
        : "=r"(_dn) : "r"(a), "r"(ph) : "memory");                             \
    while (!_dn) {                                                             \
        asm volatile("{\n\t.reg .pred p;\n\t"                                  \
            "mbarrier.try_wait.parity.acquire.cluster.shared::cta.b64 p, [%1], %2, 0x989680;\n\t" \
            "selp.b32 %0, 1, 0, p;\n\t}"                                       \
            : "=r"(_dn) : "r"(a), "r"(ph) : "memory");                         \
    }                                                                          \
} while (0)

// ---------------- SGEMM: Y[M,N] = X[M,K] @ W[N,K]^T + b1(+b2) --------------
template <int K>
__global__ __launch_bounds__(256, 2) void sgemm_bias(
    const float* __restrict__ X, const float* __restrict__ W,
    const float* __restrict__ b1, const float* __restrict__ b2,
    float* __restrict__ Y, int N)
{
    constexpr int BM = 128, BN = 64, BK = 32, SA = BK + 2;
    __shared__ float Asm[BM * SA];
    __shared__ float Wsm[BN * SA];

    const int tid = threadIdx.x;
    const int r = tid >> 4;
    const int c = tid & 15;
    const int m0 = blockIdx.y * BM;
    const int n0 = blockIdx.x * BN;

    ull acc[8][4];
#pragma unroll
    for (int i = 0; i < 8; i++)
#pragma unroll
        for (int j = 0; j < 4; j++) acc[i][j] = 0ull;

    for (int k0 = 0; k0 < K; k0 += BK) {
#pragma unroll
        for (int i = 0; i < 4; i++) {
            int f = tid + i * 256;
            int m = f >> 3, kq = f & 7;
            float4 v = *(const float4*)&X[(size_t)(m0 + m) * K + k0 + kq * 4];
            float* d = &Asm[m * SA + kq * 4];
            *(float2*)&d[0] = make_float2(v.x, v.y);
            *(float2*)&d[2] = make_float2(v.z, v.w);
        }
#pragma unroll
        for (int i = 0; i < 2; i++) {
            int f = tid + i * 256;
            int n = f >> 3, kq = f & 7;
            float4 v = *(const float4*)&W[(size_t)(n0 + n) * K + k0 + kq * 4];
            float* d = &Wsm[n * SA + kq * 4];
            *(float2*)&d[0] = make_float2(v.x, v.y);
            *(float2*)&d[2] = make_float2(v.z, v.w);
        }
        __syncthreads();

#pragma unroll
        for (int kp = 0; kp < BK / 2; kp++) {
            ull a[8], b[4];
#pragma unroll
            for (int i = 0; i < 8; i++)
                a[i] = *(const ull*)&Asm[(r * 8 + i) * SA + 2 * kp];
#pragma unroll
            for (int j = 0; j < 4; j++)
                b[j] = *(const ull*)&Wsm[(j * 16 + c) * SA + 2 * kp];
#pragma unroll
            for (int i = 0; i < 8; i++)
#pragma unroll
                for (int j = 0; j < 4; j++) FMA2(acc[i][j], a[i], b[j]);
        }
        __syncthreads();
    }

#pragma unroll
    for (int i = 0; i < 8; i++) {
        int m = m0 + r * 8 + i;
#pragma unroll
        for (int j = 0; j < 4; j++) {
            int n = n0 + j * 16 + c;
            float lo, hi;
            UNPK(lo, hi, acc[i][j]);
            float bias = b1[n];
            if (b2) bias += b2[n];
            Y[(size_t)m * N + n] = lo + hi + bias;
        }
    }
}

// ---------------- recurrent scan: dual-pipeline partial exchange -----------
// 128 CTAs = 16 clusters x 8 ranks. Each cluster runs TWO independent 2-batch
// recurrences (pipes A=batches {4c,4c+1}, B={4c+2,4c+3}) sharing the same
// register-resident W slice. Per iteration: A-FFMA -> send A partials ->
// B-FFMA -> send B -> (warps 0-3: A wait/reduce/tanh/restage) || (warps 4-7:
// B ditto) -> one __syncthreads. Each pipe's exchange latency hides under the
// other pipe's FFMA + tail. Diagonal ownership (rank r owns j & k slice r)
// means h never broadcasts; 8 x 512B bulk msgs per pipe per step.
__global__ __launch_bounds__(256) __cluster_dims__(8, 1, 1)
void rnn_scan(
    float* __restrict__ act,         // [T,B,H] pre -> overwritten with ys
    const float* __restrict__ Whh,   // [H,H] row-major (j,k)
    const float* __restrict__ h0l,   // [B,H]
    float* __restrict__ hout)        // [B,H] final hidden
{
    // slot s = pipe*2 + buf  (4 slots)
    __shared__ __align__(16) float hprt[4][8][128];   // recv partials [slot][src][b*64+j']
    __shared__ __align__(16) float sout[4][8][128];   // outgoing [slot][dest][b*64+j']
    __shared__ __align__(16) float hstage[4][128];    // own h chunk [slot][b*64+k']
    __shared__ __align__(8)  ull  mbarr[4];           // [slot]

    const int tid  = threadIdx.x;
    const int lane = tid & 31;
    const int w    = tid >> 5;       // warp = destination rank
    const int jg   = blockIdx.x & 7; // cluster rank: owns j & k slice jg
    const int bg   = blockIdx.x >> 3;
    const int b0   = bg * 4;

    // ---- persistent W slice in registers (shared by both pipes) ----
    // warp w, lane l: rows j = 64w + 2l (+1), cols k = [64*jg, 64*jg+64)
    ull w0[32], w1[32];
    {
        const float* r0 = &Whh[(size_t)(64 * w + 2 * lane + 0) * Hh + 64 * jg];
        const float* r1 = &Whh[(size_t)(64 * w + 2 * lane + 1) * Hh + 64 * jg];
#pragma unroll
        for (int kp = 0; kp < 32; kp++) {
            w0[kp] = *(const ull*)&r0[2 * kp];
            w1[kp] = *(const ull*)&r1[2 * kp];
        }
    }

    const unsigned hprt_a = cvta_smem(&hprt[0][0][0]);
    const unsigned sout_a = cvta_smem(&sout[0][0][0]);
    const unsigned bar_a  = cvta_smem(&mbarr[0]);

    // warp w sends to peer rank w; our block sits at src index jg
    const unsigned peer_hprt = mapa_u32(hprt_a, w) + (unsigned)jg * 512u;
    const unsigned peer_bar  = mapa_u32(bar_a, w);

    if (tid < 4) MBAR_INIT(bar_a + tid * 8, 1);
    __syncthreads();
    if (tid == 0) {
        asm volatile("fence.mbarrier_init.release.cluster;" ::: "memory");
        MBAR_EXPECT_TX(bar_a + 0 * 8, 4096);          // pipe0 buf0
    }
    if (tid == 128) MBAR_EXPECT_TX(bar_a + 2 * 8, 4096);  // pipe1 buf0

    // ---- per-thread tail ownership: half-CTA per pipe ----
    const int pt  = tid >> 7;            // 0: pipe A tail, 1: pipe B tail
    const int o   = tid & 127;           // output index within pipe
    const int ob  = o >> 6, oj = o & 63;
    const int gb  = b0 + 2 * pt + ob;
    const int gj  = 64 * jg + oj;

    // bootstrap: own h0 chunk (k-slice == j-slice) into buf 0 of each pipe
    hstage[pt * 2 + 0][o] = h0l[(size_t)gb * Hh + gj];
    __syncthreads();
    asm volatile("barrier.cluster.arrive.aligned;" ::: "memory");
    asm volatile("barrier.cluster.wait.aligned;" ::: "memory");

    const unsigned mybar_e = bar_a + (unsigned)(pt * 2 + 0) * 8;   // buf0
    const unsigned mybar_o = bar_a + (unsigned)(pt * 2 + 1) * 8;   // buf1
    unsigned par_e = 0, par_o = 0;

    for (int t = 0; t < Tt; t++) {
        const int buf = t & 1, nxt = buf ^ 1;
        const int sA = buf, sB = 2 + buf;            // slots this step
        size_t gidx = (size_t)t * Bb * Hh + (size_t)gb * Hh + gj;
        float pre = act[gidx];                       // overlaps FFMA

        if (t < Tt - 1) {                            // arm next step's barriers
            if (tid == 0)   MBAR_EXPECT_TX(bar_a + (unsigned)nxt * 8, 4096);
            if (tid == 128) MBAR_EXPECT_TX(bar_a + (unsigned)(2 + nxt) * 8, 4096);
        }

        // ================= pipe A: FFMA + send =================
        {
            const float* hb = hstage[sA];
            ull a00 = 0, a01 = 0, a10 = 0, a11 = 0;
#pragma unroll
            for (int kp = 0; kp < 32; kp++) {
                ull wa = w0[kp], wb = w1[kp];
                ull hb0 = *(const ull*)&hb[2 * kp];
                ull hb1 = *(const ull*)&hb[64 + 2 * kp];
                FMA2(a00, wa, hb0); FMA2(a01, wb, hb0);
                FMA2(a10, wa, hb1); FMA2(a11, wb, hb1);
            }
            float lo, hi, s0, s1;
            float* sp = &sout[sA][w][2 * lane];
            UNPK(lo, hi, a00); s0 = lo + hi; UNPK(lo, hi, a01); s1 = lo + hi;
            *(float2*)&sp[0] = make_float2(s0, s1);
            UNPK(lo, hi, a10); s0 = lo + hi; UNPK(lo, hi, a11); s1 = lo + hi;
            *(float2*)&sp[64] = make_float2(s0, s1);
            __syncwarp();
            if (lane == 0) {
                asm volatile("fence.proxy.async.shared::cta;" ::: "memory");
                bulk_s2c(peer_hprt + (unsigned)sA * 4096u,
                         sout_a + (unsigned)(sA * 8 + w) * 512u,
                         512u, peer_bar + (unsigned)sA * 8u);
            }
        }
        // ================= pipe B: FFMA + send =================
        {
            const float* hb = hstage[sB];
            ull a00 = 0, a01 = 0, a10 = 0, a11 = 0;
#pragma unroll
            for (int kp = 0; kp < 32; kp++) {
                ull wa = w0[kp], wb = w1[kp];
                ull hb0 = *(const ull*)&hb[2 * kp];
                ull hb1 = *(const ull*)&hb[64 + 2 * kp];
                FMA2(a00, wa, hb0); FMA2(a01, wb, hb0);
                FMA2(a10, wa, hb1); FMA2(a11, wb, hb1);
            }
            float lo, hi, s0, s1;
            float* sp = &sout[sB][w][2 * lane];
            UNPK(lo, hi, a00); s0 = lo + hi; UNPK(lo, hi, a01); s1 = lo + hi;
            *(float2*)&sp[0] = make_float2(s0, s1);
            UNPK(lo, hi, a10); s0 = lo + hi; UNPK(lo, hi, a11); s1 = lo + hi;
            *(float2*)&sp[64] = make_float2(s0, s1);
            __syncwarp();
            if (lane == 0) {
                asm volatile("fence.proxy.async.shared::cta;" ::: "memory");
                bulk_s2c(peer_hprt + (unsigned)sB * 4096u,
                         sout_a + (unsigned)(sB * 8 + w) * 512u,
                         512u, peer_bar + (unsigned)sB * 8u);
            }
        }

        // ============ tails in parallel: warps 0-3 pipe A, 4-7 pipe B ======
        {
            const int slot = pt * 2 + buf;
            if (buf == 0) { MBAR_WAIT_CLUSTER(mybar_e, par_e); par_e ^= 1; }
            else          { MBAR_WAIT_CLUSTER(mybar_o, par_o); par_o ^= 1; }

            float s = 0.f;
#pragma unroll
            for (int q = 0; q < 8; q++) s += hprt[slot][q][o];

            float v = tanhf(s + pre);
            act[gidx] = v;                                    // ys in place
            if (t < Tt - 1) hstage[pt * 2 + nxt][o] = v;      // next k-input
            else            hout[(size_t)gb * Hh + gj] = v;   // final hidden
        }
        __syncthreads();     // publish both pipes' hstage for next iteration
    }

    // no peer may exit while another could still address its smem
    asm volatile("barrier.cluster.arrive.aligned;" ::: "memory");
    asm volatile("barrier.cluster.wait.aligned;" ::: "memory");
}

// ---------------- launch ----------------------------------------------------
extern "C" void kernel_launch(void* const* d_in, const int* in_sizes, int n_in,
                              void* d_out, int out_size)
{
    (void)in_sizes; (void)n_in; (void)out_size;
    const float* x     = (const float*)d_in[0];   // [T,B,IN]
    const float* h0    = (const float*)d_in[1];   // [L,B,H]
    const float* W_ih0 = (const float*)d_in[2];   // [H,IN]
    const float* W_ihr = (const float*)d_in[3];   // [L-1,H,H]
    const float* W_hh  = (const float*)d_in[4];   // [L,H,H]
    const float* b_ih  = (const float*)d_in[5];   // [L,H]
    const float* b_hh  = (const float*)d_in[6];   // [L,H]
    const float* lin_W = (const float*)d_in[7];   // [OUT,H]
    const float* lin_b = (const float*)d_in[8];   // [OUT]

    float* out   = (float*)d_out;                       // [T,B,OUT]
    float* h_out = out + (size_t)Tt * Bb * OUTN;        // [L,B,H]

    float *bufA, *bufB;
    cudaGetSymbolAddress((void**)&bufA, g_bufA);
    cudaGetSymbolAddress((void**)&bufB, g_bufB);

    dim3 blk(256);
    const int MB = (Tt * Bb) / 128;     // 256 M-blocks

    // layer 0
    sgemm_bias<INN><<<dim3(Hh / 64, MB), blk>>>(x, W_ih0, b_ih, b_hh, bufA, Hh);
    rnn_scan<<<128, blk>>>(bufA, W_hh, h0, h_out);

    // layer 1
    sgemm_bias<Hh><<<dim3(Hh / 64, MB), blk>>>(bufA, W_ihr, b_ih + Hh, b_hh + Hh,
                                               bufB, Hh);
    rnn_scan<<<128, blk>>>(bufB, W_hh + Hh * Hh, h0 + Bb * Hh, h_out + Bb * Hh);

    // layer 2
    sgemm_bias<Hh><<<dim3(Hh / 64, MB), blk>>>(bufB, W_ihr + Hh * Hh,
                                               b_ih + 2 * Hh, b_hh + 2 * Hh,
                                               bufA, Hh);
    rnn_scan<<<128, blk>>>(bufA, W_hh + 2 * Hh * Hh, h0 + 2 * Bb * Hh,
                           h_out + 2 * Bb * Hh);

    // final linear: [32768,512] @ [128,512]^T + lin_b -> d_out
    sgemm_bias<Hh><<<dim3(OUTN / 64, MB), blk>>>(bufA, lin_W, lin_b, nullptr,
                                                 out, OUTN);
}